// round 5
// baseline (speedup 1.0000x reference)
#include <cuda_runtime.h>
#include <cuda_bf16.h>
#include <math.h>
#include <stdint.h>

// Problem constants
#define Bz 32
#define Sz 512
#define Hz 1024
#define Lz 2
#define WD 4
#define Mz (Bz*Sz)        // 16384 rows
#define N2 (2*Hz)         // 2048 proj cols

#define SW128(off) ((off) ^ (((off) >> 3) & 0x70))

__device__ __forceinline__ uint32_t smem_to_u32(const void* p) {
    uint32_t a;
    asm("{ .reg .u64 t; cvta.to.shared.u64 t, %1; cvt.u32.u64 %0, t; }" : "=r"(a) : "l"(p));
    return a;
}

__device__ __forceinline__ void cpasync16(uint32_t dst, const void* src) {
    asm volatile("cp.async.cg.shared.global [%0], [%1], 16;" :: "r"(dst), "l"(src));
}
#define CP_COMMIT() asm volatile("cp.async.commit_group;" ::: "memory")
#define CP_WAIT(n)  asm volatile("cp.async.wait_group %0;" :: "n"(n) : "memory")

__device__ __forceinline__ void ldsm4(uint32_t* r, uint32_t addr) {
    asm volatile("ldmatrix.sync.aligned.m8n8.x4.shared.b16 {%0,%1,%2,%3}, [%4];"
        : "=r"(r[0]), "=r"(r[1]), "=r"(r[2]), "=r"(r[3]) : "r"(addr));
}

__device__ __forceinline__ void mma16816(float* c, const uint32_t* a, const uint32_t* b) {
    asm volatile("mma.sync.aligned.m16n8k16.row.col.f32.bf16.bf16.f32 "
        "{%0,%1,%2,%3}, {%4,%5,%6,%7}, {%8,%9}, {%0,%1,%2,%3};"
        : "+f"(c[0]), "+f"(c[1]), "+f"(c[2]), "+f"(c[3])
        : "r"(a[0]), "r"(a[1]), "r"(a[2]), "r"(a[3]), "r"(b[0]), "r"(b[1]));
}

// ---------------------------------------------------------------------------
// Scratch (device globals, allocation-free)
// ---------------------------------------------------------------------------
__device__ float          g_fo[(size_t)Mz * Hz];
__device__ float          g_bo[(size_t)Mz * Hz];
__device__ float          g_x [(size_t)Mz * Hz];
__device__ __nv_bfloat16  g_xhi[(size_t)Mz * Hz];
__device__ __nv_bfloat16  g_xlo[(size_t)Mz * Hz];
// Transposed split weights: [widx=8][jblk=8][nn=256][k=1024]
// nn interleave: for hidden col h' (0..127): nl at (h'>>3)*16 + (h'&7),
//                gate at same + 8.
__device__ __nv_bfloat16  g_Whi[(size_t)8 * 2048 * 1024];
__device__ __nv_bfloat16  g_Wlo[(size_t)8 * 2048 * 1024];

// ---------------------------------------------------------------------------
__global__ void init_kernel(const float* __restrict__ inp) {
    size_t i = (size_t)blockIdx.x * blockDim.x + threadIdx.x;
    float4 v = ((const float4*)inp)[i];
    ((float4*)g_fo)[i] = v;
    ((float4*)g_bo)[i] = v;
}

// ---------------------------------------------------------------------------
// prep_w: transpose + bf16-split + nl/gate 8-col interleave
// widx = dir*4 + l*2 + hw
// ---------------------------------------------------------------------------
__global__ void prep_w_kernel(const float* __restrict__ fw_W,
                              const float* __restrict__ bw_W) {
    int widx = blockIdx.z;
    const float* W = (widx >= 4 ? bw_W : fw_W) +
                     ((size_t)((widx >> 1) & 1) * 2 + (widx & 1)) * Hz * N2;
    __shared__ float tile[32][33];
    int k0 = blockIdx.y * 32, n0 = blockIdx.x * 32;
    int tx = threadIdx.x, ty = threadIdx.y;
#pragma unroll
    for (int i = 0; i < 4; i++) {
        int ky = ty + 8 * i;
        tile[ky][tx] = W[(size_t)(k0 + ky) * N2 + n0 + tx];
    }
    __syncthreads();
#pragma unroll
    for (int i = 0; i < 4; i++) {
        int ny = ty + 8 * i;
        int n = n0 + ny;
        int h = n & 1023;
        int half = n >> 10;           // 0 = nl, 1 = gate
        int jb = h >> 7;
        int hp = h & 127;
        int p = (hp >> 3) * 16 + (hp & 7) + half * 8;
        size_t orow = ((size_t)widx * 2048 + jb * 256 + p) * Hz + k0 + tx;
        float v = tile[tx][ny];
        __nv_bfloat16 hi = __float2bfloat16(v);
        g_Whi[orow] = hi;
        g_Wlo[orow] = __float2bfloat16(v - __bfloat162float(hi));
    }
}

// ---------------------------------------------------------------------------
// window sum -> g_x (float) + g_xhi/g_xlo (bf16 split)
// ---------------------------------------------------------------------------
__global__ void wsum_kernel(const float* __restrict__ pf,
                            const float* __restrict__ pb,
                            const float* __restrict__ w5, int dir) {
    const float* o = dir ? g_bo : g_fo;
    int m  = blockIdx.x;
    int t  = m & (Sz - 1);
    int h4 = threadIdx.x;
    float4 acc = make_float4(0.f, 0.f, 0.f, 0.f);
#pragma unroll
    for (int k = 0; k <= WD; k++) {
        int p = t + k + (dir ? 0 : -WD);
        const float4* src;
        if (p < 0)        src = (const float4*)(pf + (size_t)(p + WD) * Hz);
        else if (p >= Sz) src = (const float4*)(pb + (size_t)(p - Sz) * Hz);
        else              src = (const float4*)(o  + (size_t)(m - t + p) * Hz);
        float wk = w5[k];
        float4 v = src[h4];
        acc.x += wk * v.x; acc.y += wk * v.y;
        acc.z += wk * v.z; acc.w += wk * v.w;
    }
    size_t o4 = (size_t)m * (Hz / 4) + h4;
    ((float4*)g_x)[o4] = acc;
    __nv_bfloat16 h0 = __float2bfloat16(acc.x), h1 = __float2bfloat16(acc.y);
    __nv_bfloat16 h2 = __float2bfloat16(acc.z), h3 = __float2bfloat16(acc.w);
    ((__nv_bfloat162*)g_xhi)[o4 * 2 + 0] = __halves2bfloat162(h0, h1);
    ((__nv_bfloat162*)g_xhi)[o4 * 2 + 1] = __halves2bfloat162(h2, h3);
    ((__nv_bfloat162*)g_xlo)[o4 * 2 + 0] = __halves2bfloat162(
        __float2bfloat16(acc.x - __bfloat162float(h0)),
        __float2bfloat16(acc.y - __bfloat162float(h1)));
    ((__nv_bfloat162*)g_xlo)[o4 * 2 + 1] = __halves2bfloat162(
        __float2bfloat16(acc.z - __bfloat162float(h2)),
        __float2bfloat16(acc.w - __bfloat162float(h3)));
}

// ---------------------------------------------------------------------------
// bf16 mma.sync GEMM + fused highway epilogue.
// CTA: 128 M x 256 (interleaved nl/gate), 512 thr, 16 warps (4 M x 4 N),
// warp tile 32x64, BK=64, 2-stage cp.async pipeline, bf16-split (3 products).
// ---------------------------------------------------------------------------
#define OFF_A   0
#define OFF_ALO 16384
#define OFF_B   32768
#define OFF_BLO 65536
#define STAGE   98304
#define SMEM_BYTES (2 * STAGE)   // 196608

__global__ void __launch_bounds__(512, 1)
gemm_hw_kernel(const float* __restrict__ bias, float* __restrict__ out,
               int widx, int l, int dir, int mode) {
    extern __shared__ char sm[];
    uint32_t sb = smem_to_u32(sm);
    int tid = threadIdx.x, wid = tid >> 5, lane = tid & 31;
    int wy = wid & 3, wx = wid >> 2;
    int jcta = blockIdx.x;
    int m0 = blockIdx.y * 128;
    const size_t wbase = (size_t)widx * 2048 * 1024 + (size_t)jcta * 256 * 1024;

    float acc[2][8][4];
#pragma unroll
    for (int mt = 0; mt < 2; mt++)
#pragma unroll
        for (int j = 0; j < 8; j++)
#pragma unroll
            for (int e = 0; e < 4; e++) acc[mt][j][e] = 0.f;

    // lane-invariant pieces of ldmatrix addresses
    int a_row  = wy * 32 + (lane & 15);           // + mt*16
    int a_colb = (lane >> 4) * 16;                // + ks*32
    int b_row  = wx * 64 + ((lane >> 4) << 3) + (lane & 7);  // + jp*16
    int b_colb = ((lane >> 3) & 1) * 16;          // + ks*32

    // ---- loader lambda-ish macro ----
#define LOAD_STAGE(c, stg) do { \
    int cc = (c); uint32_t so_base = (stg); \
    _Pragma("unroll") \
    for (int i = 0; i < 2; i++) { \
        int idx = tid + 512 * i; int row = idx >> 3, q = idx & 7; \
        size_t g = (size_t)(m0 + row) * Hz + cc * 64 + q * 8; \
        uint32_t so = SW128((uint32_t)(row * 128 + q * 16)); \
        cpasync16(sb + so_base + OFF_A + so, g_xhi + g); \
        cpasync16(sb + so_base + OFF_ALO + so, g_xlo + g); \
    } \
    _Pragma("unroll") \
    for (int i = 0; i < 4; i++) { \
        int idx = tid + 512 * i; int row = idx >> 3, q = idx & 7; \
        size_t g = wbase + (size_t)row * Hz + cc * 64 + q * 8; \
        uint32_t so = SW128((uint32_t)(row * 128 + q * 16)); \
        cpasync16(sb + so_base + OFF_B + so, g_Whi + g); \
        cpasync16(sb + so_base + OFF_BLO + so, g_Wlo + g); \
    } \
    CP_COMMIT(); \
} while (0)

    LOAD_STAGE(0, 0);

    for (int c = 0; c < 16; c++) {
        uint32_t stg = (c & 1) * STAGE;
        if (c + 1 < 16) {
            LOAD_STAGE(c + 1, ((c + 1) & 1) * STAGE);
            CP_WAIT(1);
        } else {
            CP_WAIT(0);
        }
        __syncthreads();

#pragma unroll
        for (int ks = 0; ks < 4; ks++) {
            uint32_t Ah[2][4], Al[2][4];
#pragma unroll
            for (int mt = 0; mt < 2; mt++) {
                uint32_t off = SW128((uint32_t)((a_row + mt * 16) * 128 +
                                                a_colb + ks * 32));
                ldsm4(Ah[mt], sb + stg + OFF_A + off);
                ldsm4(Al[mt], sb + stg + OFF_ALO + off);
            }
            uint32_t Bh[4][4], Bl[4][4];
#pragma unroll
            for (int jp = 0; jp < 4; jp++) {
                uint32_t off = SW128((uint32_t)((b_row + jp * 16) * 128 +
                                                b_colb + ks * 32));
                ldsm4(Bh[jp], sb + stg + OFF_B + off);
                ldsm4(Bl[jp], sb + stg + OFF_BLO + off);
            }
#pragma unroll
            for (int mt = 0; mt < 2; mt++)
#pragma unroll
                for (int jp = 0; jp < 4; jp++) {
                    mma16816(acc[mt][2 * jp],     Ah[mt], Bh[jp] + 0);
                    mma16816(acc[mt][2 * jp + 1], Ah[mt], Bh[jp] + 2);
                    mma16816(acc[mt][2 * jp],     Al[mt], Bh[jp] + 0);
                    mma16816(acc[mt][2 * jp + 1], Al[mt], Bh[jp] + 2);
                    mma16816(acc[mt][2 * jp],     Ah[mt], Bl[jp] + 0);
                    mma16816(acc[mt][2 * jp + 1], Ah[mt], Bl[jp] + 2);
                }
        }
        __syncthreads();
    }

    // ---- fused highway epilogue (in registers) ----
    float* state = dir ? g_bo : g_fo;
#pragma unroll
    for (int mt = 0; mt < 2; mt++) {
        int r0 = m0 + wy * 32 + mt * 16 + (lane >> 2);
#pragma unroll
        for (int p = 0; p < 4; p++) {
            int h = jcta * 128 + wx * 32 + p * 8 + (lane & 3) * 2;
            float bn0 = bias[h],        bn1 = bias[h + 1];
            float bg0 = bias[1024 + h], bg1 = bias[1024 + h + 1];
            const float* nlr = acc[mt][2 * p];
            const float* gr  = acc[mt][2 * p + 1];
#pragma unroll
            for (int hf = 0; hf < 2; hf++) {
                int r = r0 + hf * 8;
                size_t gp = (size_t)r * Hz + h;
                float nl0 = nlr[hf * 2 + 0] + bn0;
                float nl1 = nlr[hf * 2 + 1] + bn1;
                float gg0 = gr[hf * 2 + 0] + bg0;
                float gg1 = gr[hf * 2 + 1] + bg1;
                float gs0 = 1.f / (1.f + __expf(-gg0));
                float gs1 = 1.f / (1.f + __expf(-gg1));
                float2 xo = *(const float2*)(g_x + gp);
                float r0v = gs0 * xo.x + (1.f - gs0) * fmaxf(nl0, 0.f);
                float r1v = gs1 * xo.y + (1.f - gs1) * fmaxf(nl1, 0.f);
                if (mode == 0) {
                    *(float2*)(g_x + gp) = make_float2(r0v, r1v);
                    __nv_bfloat16 b0 = __float2bfloat16(r0v);
                    __nv_bfloat16 b1 = __float2bfloat16(r1v);
                    ((__nv_bfloat162*)g_xhi)[gp / 2] = __halves2bfloat162(b0, b1);
                    ((__nv_bfloat162*)g_xlo)[gp / 2] = __halves2bfloat162(
                        __float2bfloat16(r0v - __bfloat162float(b0)),
                        __float2bfloat16(r1v - __bfloat162float(b1)));
                } else {
                    if (l) {
                        float2 st = *(const float2*)(state + gp);
                        r0v += st.x; r1v += st.y;
                    }
                    *(float2*)(state + gp) = make_float2(r0v, r1v);
                    *(float2*)(out + ((size_t)l * Mz + r) * N2 +
                               (size_t)dir * Hz + h) = make_float2(r0v, r1v);
                }
            }
        }
    }
}

// ---------------------------------------------------------------------------
extern "C" void kernel_launch(void* const* d_in, const int* in_sizes, int n_in,
                              void* d_out, int out_size) {
    const float* inputs = (const float*)d_in[0];
    const float* fw_pad = (const float*)d_in[2];
    const float* bw_pad = (const float*)d_in[3];
    const float* fw_w   = (const float*)d_in[4];
    const float* bw_w   = (const float*)d_in[5];
    const float* fw_W   = (const float*)d_in[6];
    const float* fw_b   = (const float*)d_in[7];
    const float* bw_W   = (const float*)d_in[8];
    const float* bw_b   = (const float*)d_in[9];
    float* out = (float*)d_out;

    cudaFuncSetAttribute(gemm_hw_kernel,
                         cudaFuncAttributeMaxDynamicSharedMemorySize, SMEM_BYTES);

    prep_w_kernel<<<dim3(64, 32, 8), dim3(32, 8)>>>(fw_W, bw_W);
    init_kernel<<<(size_t)Mz * Hz / 4 / 256, 256>>>(inputs);

    for (int l = 0; l < Lz; l++) {
        for (int dir = 0; dir < 2; dir++) {
            const float* bl = (dir ? bw_b : fw_b) + (size_t)l * 2 * N2;
            const float* wv = (dir ? bw_w : fw_w) + (size_t)l * (WD + 1);

            wsum_kernel<<<Mz, 256>>>(fw_pad + (size_t)l * WD * Hz,
                                     bw_pad + (size_t)l * WD * Hz, wv, dir);
            for (int hw = 0; hw < 2; hw++) {
                int widx = dir * 4 + l * 2 + hw;
                gemm_hw_kernel<<<dim3(8, 128), 512, SMEM_BYTES>>>(
                    bl + (size_t)hw * N2, out, widx, l, dir, hw);
            }
        }
    }
}

// round 6
// speedup vs baseline: 1.0031x; 1.0031x over previous
#include <cuda_runtime.h>
#include <cuda_bf16.h>
#include <math.h>
#include <stdint.h>

// Problem constants
#define Bz 32
#define Sz 512
#define Hz 1024
#define Lz 2
#define WD 4
#define Mz (Bz*Sz)        // 16384 rows
#define N2 (2*Hz)         // 2048 proj cols

#define SW128(off) ((off) ^ (((off) >> 3) & 0x70))

__device__ __forceinline__ uint32_t smem_to_u32(const void* p) {
    uint32_t a;
    asm("{ .reg .u64 t; cvta.to.shared.u64 t, %1; cvt.u32.u64 %0, t; }" : "=r"(a) : "l"(p));
    return a;
}

__device__ __forceinline__ void cpasync16(uint32_t dst, const void* src) {
    asm volatile("cp.async.cg.shared.global [%0], [%1], 16;" :: "r"(dst), "l"(src));
}
#define CP_COMMIT() asm volatile("cp.async.commit_group;" ::: "memory")
#define CP_WAIT(n)  asm volatile("cp.async.wait_group %0;" :: "n"(n) : "memory")

__device__ __forceinline__ void ldsm4(uint32_t* r, uint32_t addr) {
    asm volatile("ldmatrix.sync.aligned.m8n8.x4.shared.b16 {%0,%1,%2,%3}, [%4];"
        : "=r"(r[0]), "=r"(r[1]), "=r"(r[2]), "=r"(r[3]) : "r"(addr));
}

__device__ __forceinline__ void mma16816(float* c, const uint32_t* a, const uint32_t* b) {
    asm volatile("mma.sync.aligned.m16n8k16.row.col.f32.bf16.bf16.f32 "
        "{%0,%1,%2,%3}, {%4,%5,%6,%7}, {%8,%9}, {%0,%1,%2,%3};"
        : "+f"(c[0]), "+f"(c[1]), "+f"(c[2]), "+f"(c[3])
        : "r"(a[0]), "r"(a[1]), "r"(a[2]), "r"(a[3]), "r"(b[0]), "r"(b[1]));
}

// ---------------------------------------------------------------------------
// Scratch (device globals, allocation-free)
// ---------------------------------------------------------------------------
__device__ float          g_fo[(size_t)Mz * Hz];
__device__ float          g_bo[(size_t)Mz * Hz];
__device__ float          g_x [(size_t)Mz * Hz];
__device__ __nv_bfloat16  g_xhi[(size_t)Mz * Hz];
__device__ __nv_bfloat16  g_xlo[(size_t)Mz * Hz];
// Transposed split weights: [widx=8][jblk=8][nn=256][k=1024]
// nn interleave: for hidden col h' (0..127): nl at (h'>>3)*16 + (h'&7),
//                gate at same + 8.
__device__ __nv_bfloat16  g_Whi[(size_t)8 * 2048 * 1024];
__device__ __nv_bfloat16  g_Wlo[(size_t)8 * 2048 * 1024];

// ---------------------------------------------------------------------------
__global__ void init_kernel(const float* __restrict__ inp) {
    size_t i = (size_t)blockIdx.x * blockDim.x + threadIdx.x;
    float4 v = ((const float4*)inp)[i];
    ((float4*)g_fo)[i] = v;
    ((float4*)g_bo)[i] = v;
}

// ---------------------------------------------------------------------------
// prep_w: transpose + bf16-split + nl/gate 8-col interleave
// widx = dir*4 + l*2 + hw
// ---------------------------------------------------------------------------
__global__ void prep_w_kernel(const float* __restrict__ fw_W,
                              const float* __restrict__ bw_W) {
    int widx = blockIdx.z;
    const float* W = (widx >= 4 ? bw_W : fw_W) +
                     ((size_t)((widx >> 1) & 1) * 2 + (widx & 1)) * Hz * N2;
    __shared__ float tile[32][33];
    int k0 = blockIdx.y * 32, n0 = blockIdx.x * 32;
    int tx = threadIdx.x, ty = threadIdx.y;
#pragma unroll
    for (int i = 0; i < 4; i++) {
        int ky = ty + 8 * i;
        tile[ky][tx] = W[(size_t)(k0 + ky) * N2 + n0 + tx];
    }
    __syncthreads();
#pragma unroll
    for (int i = 0; i < 4; i++) {
        int ny = ty + 8 * i;
        int n = n0 + ny;
        int h = n & 1023;
        int half = n >> 10;           // 0 = nl, 1 = gate
        int jb = h >> 7;
        int hp = h & 127;
        int p = (hp >> 3) * 16 + (hp & 7) + half * 8;
        size_t orow = ((size_t)widx * 2048 + jb * 256 + p) * Hz + k0 + tx;
        float v = tile[tx][ny];
        __nv_bfloat16 hi = __float2bfloat16(v);
        g_Whi[orow] = hi;
        g_Wlo[orow] = __float2bfloat16(v - __bfloat162float(hi));
    }
}

// ---------------------------------------------------------------------------
// window sum -> g_x (float) + g_xhi/g_xlo (bf16 split)
// ---------------------------------------------------------------------------
__global__ void wsum_kernel(const float* __restrict__ pf,
                            const float* __restrict__ pb,
                            const float* __restrict__ w5, int dir) {
    const float* o = dir ? g_bo : g_fo;
    int m  = blockIdx.x;
    int t  = m & (Sz - 1);
    int h4 = threadIdx.x;
    float4 acc = make_float4(0.f, 0.f, 0.f, 0.f);
#pragma unroll
    for (int k = 0; k <= WD; k++) {
        int p = t + k + (dir ? 0 : -WD);
        const float4* src;
        if (p < 0)        src = (const float4*)(pf + (size_t)(p + WD) * Hz);
        else if (p >= Sz) src = (const float4*)(pb + (size_t)(p - Sz) * Hz);
        else              src = (const float4*)(o  + (size_t)(m - t + p) * Hz);
        float wk = w5[k];
        float4 v = src[h4];
        acc.x += wk * v.x; acc.y += wk * v.y;
        acc.z += wk * v.z; acc.w += wk * v.w;
    }
    size_t o4 = (size_t)m * (Hz / 4) + h4;
    ((float4*)g_x)[o4] = acc;
    __nv_bfloat16 h0 = __float2bfloat16(acc.x), h1 = __float2bfloat16(acc.y);
    __nv_bfloat16 h2 = __float2bfloat16(acc.z), h3 = __float2bfloat16(acc.w);
    ((__nv_bfloat162*)g_xhi)[o4 * 2 + 0] = __halves2bfloat162(h0, h1);
    ((__nv_bfloat162*)g_xhi)[o4 * 2 + 1] = __halves2bfloat162(h2, h3);
    ((__nv_bfloat162*)g_xlo)[o4 * 2 + 0] = __halves2bfloat162(
        __float2bfloat16(acc.x - __bfloat162float(h0)),
        __float2bfloat16(acc.y - __bfloat162float(h1)));
    ((__nv_bfloat162*)g_xlo)[o4 * 2 + 1] = __halves2bfloat162(
        __float2bfloat16(acc.z - __bfloat162float(h2)),
        __float2bfloat16(acc.w - __bfloat162float(h3)));
}

// ---------------------------------------------------------------------------
// bf16 mma.sync GEMM + fused highway epilogue.
// CTA: 128 M x 256 (interleaved nl/gate), 512 thr, 16 warps (4 M x 4 N),
// warp tile 32x64, BK=64, 2-stage cp.async pipeline, bf16-split (3 products).
// ---------------------------------------------------------------------------
#define OFF_A   0
#define OFF_ALO 16384
#define OFF_B   32768
#define OFF_BLO 65536
#define STAGE   98304
#define SMEM_BYTES (2 * STAGE)   // 196608

__global__ void __launch_bounds__(512, 1)
gemm_hw_kernel(const float* __restrict__ bias, float* __restrict__ out,
               int widx, int l, int dir, int mode) {
    extern __shared__ char sm[];
    uint32_t sb = smem_to_u32(sm);
    int tid = threadIdx.x, wid = tid >> 5, lane = tid & 31;
    int wy = wid & 3, wx = wid >> 2;
    int jcta = blockIdx.x;
    int m0 = blockIdx.y * 128;
    const size_t wbase = (size_t)widx * 2048 * 1024 + (size_t)jcta * 256 * 1024;

    float acc[2][8][4];
#pragma unroll
    for (int mt = 0; mt < 2; mt++)
#pragma unroll
        for (int j = 0; j < 8; j++)
#pragma unroll
            for (int e = 0; e < 4; e++) acc[mt][j][e] = 0.f;

    // lane-invariant pieces of ldmatrix addresses
    int a_row  = wy * 32 + (lane & 15);           // + mt*16
    int a_colb = (lane >> 4) * 16;                // + ks*32
    int b_row  = wx * 64 + ((lane >> 4) << 3) + (lane & 7);  // + jp*16
    int b_colb = ((lane >> 3) & 1) * 16;          // + ks*32

    // ---- loader lambda-ish macro ----
#define LOAD_STAGE(c, stg) do { \
    int cc = (c); uint32_t so_base = (stg); \
    _Pragma("unroll") \
    for (int i = 0; i < 2; i++) { \
        int idx = tid + 512 * i; int row = idx >> 3, q = idx & 7; \
        size_t g = (size_t)(m0 + row) * Hz + cc * 64 + q * 8; \
        uint32_t so = SW128((uint32_t)(row * 128 + q * 16)); \
        cpasync16(sb + so_base + OFF_A + so, g_xhi + g); \
        cpasync16(sb + so_base + OFF_ALO + so, g_xlo + g); \
    } \
    _Pragma("unroll") \
    for (int i = 0; i < 4; i++) { \
        int idx = tid + 512 * i; int row = idx >> 3, q = idx & 7; \
        size_t g = wbase + (size_t)row * Hz + cc * 64 + q * 8; \
        uint32_t so = SW128((uint32_t)(row * 128 + q * 16)); \
        cpasync16(sb + so_base + OFF_B + so, g_Whi + g); \
        cpasync16(sb + so_base + OFF_BLO + so, g_Wlo + g); \
    } \
    CP_COMMIT(); \
} while (0)

    LOAD_STAGE(0, 0);

    for (int c = 0; c < 16; c++) {
        uint32_t stg = (c & 1) * STAGE;
        if (c + 1 < 16) {
            LOAD_STAGE(c + 1, ((c + 1) & 1) * STAGE);
            CP_WAIT(1);
        } else {
            CP_WAIT(0);
        }
        __syncthreads();

#pragma unroll
        for (int ks = 0; ks < 4; ks++) {
            uint32_t Ah[2][4], Al[2][4];
#pragma unroll
            for (int mt = 0; mt < 2; mt++) {
                uint32_t off = SW128((uint32_t)((a_row + mt * 16) * 128 +
                                                a_colb + ks * 32));
                ldsm4(Ah[mt], sb + stg + OFF_A + off);
                ldsm4(Al[mt], sb + stg + OFF_ALO + off);
            }
            uint32_t Bh[4][4], Bl[4][4];
#pragma unroll
            for (int jp = 0; jp < 4; jp++) {
                uint32_t off = SW128((uint32_t)((b_row + jp * 16) * 128 +
                                                b_colb + ks * 32));
                ldsm4(Bh[jp], sb + stg + OFF_B + off);
                ldsm4(Bl[jp], sb + stg + OFF_BLO + off);
            }
#pragma unroll
            for (int mt = 0; mt < 2; mt++)
#pragma unroll
                for (int jp = 0; jp < 4; jp++) {
                    mma16816(acc[mt][2 * jp],     Ah[mt], Bh[jp] + 0);
                    mma16816(acc[mt][2 * jp + 1], Ah[mt], Bh[jp] + 2);
                    mma16816(acc[mt][2 * jp],     Al[mt], Bh[jp] + 0);
                    mma16816(acc[mt][2 * jp + 1], Al[mt], Bh[jp] + 2);
                    mma16816(acc[mt][2 * jp],     Ah[mt], Bl[jp] + 0);
                    mma16816(acc[mt][2 * jp + 1], Ah[mt], Bl[jp] + 2);
                }
        }
        __syncthreads();
    }

    // ---- fused highway epilogue (in registers) ----
    float* state = dir ? g_bo : g_fo;
#pragma unroll
    for (int mt = 0; mt < 2; mt++) {
        int r0 = m0 + wy * 32 + mt * 16 + (lane >> 2);
#pragma unroll
        for (int p = 0; p < 4; p++) {
            int h = jcta * 128 + wx * 32 + p * 8 + (lane & 3) * 2;
            float bn0 = bias[h],        bn1 = bias[h + 1];
            float bg0 = bias[1024 + h], bg1 = bias[1024 + h + 1];
            const float* nlr = acc[mt][2 * p];
            const float* gr  = acc[mt][2 * p + 1];
#pragma unroll
            for (int hf = 0; hf < 2; hf++) {
                int r = r0 + hf * 8;
                size_t gp = (size_t)r * Hz + h;
                float nl0 = nlr[hf * 2 + 0] + bn0;
                float nl1 = nlr[hf * 2 + 1] + bn1;
                float gg0 = gr[hf * 2 + 0] + bg0;
                float gg1 = gr[hf * 2 + 1] + bg1;
                float gs0 = 1.f / (1.f + __expf(-gg0));
                float gs1 = 1.f / (1.f + __expf(-gg1));
                float2 xo = *(const float2*)(g_x + gp);
                float r0v = gs0 * xo.x + (1.f - gs0) * fmaxf(nl0, 0.f);
                float r1v = gs1 * xo.y + (1.f - gs1) * fmaxf(nl1, 0.f);
                if (mode == 0) {
                    *(float2*)(g_x + gp) = make_float2(r0v, r1v);
                    __nv_bfloat16 b0 = __float2bfloat16(r0v);
                    __nv_bfloat16 b1 = __float2bfloat16(r1v);
                    ((__nv_bfloat162*)g_xhi)[gp / 2] = __halves2bfloat162(b0, b1);
                    ((__nv_bfloat162*)g_xlo)[gp / 2] = __halves2bfloat162(
                        __float2bfloat16(r0v - __bfloat162float(b0)),
                        __float2bfloat16(r1v - __bfloat162float(b1)));
                } else {
                    if (l) {
                        float2 st = *(const float2*)(state + gp);
                        r0v += st.x; r1v += st.y;
                    }
                    *(float2*)(state + gp) = make_float2(r0v, r1v);
                    *(float2*)(out + ((size_t)l * Mz + r) * N2 +
                               (size_t)dir * Hz + h) = make_float2(r0v, r1v);
                }
            }
        }
    }
}

// ---------------------------------------------------------------------------
extern "C" void kernel_launch(void* const* d_in, const int* in_sizes, int n_in,
                              void* d_out, int out_size) {
    const float* inputs = (const float*)d_in[0];
    const float* fw_pad = (const float*)d_in[2];
    const float* bw_pad = (const float*)d_in[3];
    const float* fw_w   = (const float*)d_in[4];
    const float* bw_w   = (const float*)d_in[5];
    const float* fw_W   = (const float*)d_in[6];
    const float* fw_b   = (const float*)d_in[7];
    const float* bw_W   = (const float*)d_in[8];
    const float* bw_b   = (const float*)d_in[9];
    float* out = (float*)d_out;

    cudaFuncSetAttribute(gemm_hw_kernel,
                         cudaFuncAttributeMaxDynamicSharedMemorySize, SMEM_BYTES);

    prep_w_kernel<<<dim3(64, 32, 8), dim3(32, 8)>>>(fw_W, bw_W);
    init_kernel<<<(size_t)Mz * Hz / 4 / 256, 256>>>(inputs);

    for (int l = 0; l < Lz; l++) {
        for (int dir = 0; dir < 2; dir++) {
            const float* bl = (dir ? bw_b : fw_b) + (size_t)l * 2 * N2;
            const float* wv = (dir ? bw_w : fw_w) + (size_t)l * (WD + 1);

            wsum_kernel<<<Mz, 256>>>(fw_pad + (size_t)l * WD * Hz,
                                     bw_pad + (size_t)l * WD * Hz, wv, dir);
            for (int hw = 0; hw < 2; hw++) {
                int widx = dir * 4 + l * 2 + hw;
                gemm_hw_kernel<<<dim3(8, 128), 512, SMEM_BYTES>>>(
                    bl + (size_t)hw * N2, out, widx, l, dir, hw);
            }
        }
    }
}

// round 7
// speedup vs baseline: 1.3174x; 1.3134x over previous
#include <cuda_runtime.h>
#include <cuda_fp16.h>
#include <math.h>
#include <stdint.h>

// Problem constants
#define Bz 32
#define Sz 512
#define Hz 1024
#define Lz 2
#define WD 4
#define Mz (Bz*Sz)        // 16384 rows
#define N2 (2*Hz)         // 2048 proj cols

#define SW128(off) ((off) ^ (((off) >> 3) & 0x70))

__device__ __forceinline__ uint32_t smem_to_u32(const void* p) {
    uint32_t a;
    asm("{ .reg .u64 t; cvta.to.shared.u64 t, %1; cvt.u32.u64 %0, t; }" : "=r"(a) : "l"(p));
    return a;
}

__device__ __forceinline__ void cpasync16(uint32_t dst, const void* src) {
    asm volatile("cp.async.cg.shared.global [%0], [%1], 16;" :: "r"(dst), "l"(src));
}
#define CP_COMMIT() asm volatile("cp.async.commit_group;" ::: "memory")
#define CP_WAIT(n)  asm volatile("cp.async.wait_group %0;" :: "n"(n) : "memory")

__device__ __forceinline__ void ldsm4(uint32_t* r, uint32_t addr) {
    asm volatile("ldmatrix.sync.aligned.m8n8.x4.shared.b16 {%0,%1,%2,%3}, [%4];"
        : "=r"(r[0]), "=r"(r[1]), "=r"(r[2]), "=r"(r[3]) : "r"(addr));
}

__device__ __forceinline__ void mma16816(float* c, const uint32_t* a, const uint32_t* b) {
    asm volatile("mma.sync.aligned.m16n8k16.row.col.f32.f16.f16.f32 "
        "{%0,%1,%2,%3}, {%4,%5,%6,%7}, {%8,%9}, {%0,%1,%2,%3};"
        : "+f"(c[0]), "+f"(c[1]), "+f"(c[2]), "+f"(c[3])
        : "r"(a[0]), "r"(a[1]), "r"(a[2]), "r"(a[3]), "r"(b[0]), "r"(b[1]));
}

// ---------------------------------------------------------------------------
// Scratch (device globals, allocation-free). Per-direction x buffers.
// ---------------------------------------------------------------------------
__device__ float   g_fo[(size_t)Mz * Hz];
__device__ float   g_bo[(size_t)Mz * Hz];
__device__ float   g_x  [2][(size_t)Mz * Hz];
__device__ __half  g_xhi[2][(size_t)Mz * Hz];
__device__ __half  g_xlo[2][(size_t)Mz * Hz];
// Transposed fp16 weights: [widx=8][jblk=8][nn=256][k=1024]
// nn interleave: hidden col h' (0..127): nl at (h'>>3)*16+(h'&7), gate +8.
__device__ __half  g_Whi[(size_t)8 * 2048 * 1024];

// ---------------------------------------------------------------------------
__global__ void init_kernel(const float* __restrict__ inp) {
    size_t i = (size_t)blockIdx.x * blockDim.x + threadIdx.x;
    float4 v = ((const float4*)inp)[i];
    ((float4*)g_fo)[i] = v;
    ((float4*)g_bo)[i] = v;
}

// ---------------------------------------------------------------------------
// prep_w: transpose + fp16 round + nl/gate 8-col interleave
// widx = dir*4 + l*2 + hw
// ---------------------------------------------------------------------------
__global__ void prep_w_kernel(const float* __restrict__ fw_W,
                              const float* __restrict__ bw_W) {
    int widx = blockIdx.z;
    const float* W = (widx >= 4 ? bw_W : fw_W) +
                     ((size_t)((widx >> 1) & 1) * 2 + (widx & 1)) * Hz * N2;
    __shared__ float tile[32][33];
    int k0 = blockIdx.y * 32, n0 = blockIdx.x * 32;
    int tx = threadIdx.x, ty = threadIdx.y;
#pragma unroll
    for (int i = 0; i < 4; i++) {
        int ky = ty + 8 * i;
        tile[ky][tx] = W[(size_t)(k0 + ky) * N2 + n0 + tx];
    }
    __syncthreads();
#pragma unroll
    for (int i = 0; i < 4; i++) {
        int ny = ty + 8 * i;
        int n = n0 + ny;
        int h = n & 1023;
        int half = n >> 10;           // 0 = nl, 1 = gate
        int jb = h >> 7;
        int hp = h & 127;
        int p = (hp >> 3) * 16 + (hp & 7) + half * 8;
        size_t orow = ((size_t)widx * 2048 + jb * 256 + p) * Hz + k0 + tx;
        g_Whi[orow] = __float2half(tile[tx][ny]);
    }
}

// ---------------------------------------------------------------------------
// window sum -> g_x[dir] (float) + g_xhi/g_xlo[dir] (fp16 split)
// blockIdx.y = dir
// ---------------------------------------------------------------------------
__global__ void wsum_kernel(const float* __restrict__ pf,
                            const float* __restrict__ pb,
                            const float* __restrict__ fw_w,
                            const float* __restrict__ bw_w) {
    int dir = blockIdx.y;
    const float* o  = dir ? g_bo : g_fo;
    const float* w5 = dir ? bw_w : fw_w;
    int m  = blockIdx.x;
    int t  = m & (Sz - 1);
    int h4 = threadIdx.x;
    float4 acc = make_float4(0.f, 0.f, 0.f, 0.f);
#pragma unroll
    for (int k = 0; k <= WD; k++) {
        int p = t + k + (dir ? 0 : -WD);
        const float4* src;
        if (p < 0)        src = (const float4*)(pf + (size_t)(p + WD) * Hz);
        else if (p >= Sz) src = (const float4*)(pb + (size_t)(p - Sz) * Hz);
        else              src = (const float4*)(o  + (size_t)(m - t + p) * Hz);
        float wk = w5[k];
        float4 v = src[h4];
        acc.x += wk * v.x; acc.y += wk * v.y;
        acc.z += wk * v.z; acc.w += wk * v.w;
    }
    size_t o4 = (size_t)m * (Hz / 4) + h4;
    ((float4*)g_x[dir])[o4] = acc;
    __half h0 = __float2half(acc.x), h1 = __float2half(acc.y);
    __half h2 = __float2half(acc.z), h3 = __float2half(acc.w);
    ((__half2*)g_xhi[dir])[o4 * 2 + 0] = __halves2half2(h0, h1);
    ((__half2*)g_xhi[dir])[o4 * 2 + 1] = __halves2half2(h2, h3);
    ((__half2*)g_xlo[dir])[o4 * 2 + 0] = __halves2half2(
        __float2half(acc.x - __half2float(h0)),
        __float2half(acc.y - __half2float(h1)));
    ((__half2*)g_xlo[dir])[o4 * 2 + 1] = __halves2half2(
        __float2half(acc.z - __half2float(h2)),
        __float2half(acc.w - __half2float(h3)));
}

// ---------------------------------------------------------------------------
// fp16 mma.sync GEMM (2-product split: Ahi*Whi + Alo*Whi) + fused highway.
// CTA: 128 M x 256 (interleaved nl/gate), 512 thr, 16 warps (4M x 4N),
// warp tile 32x64, BK=64, 3-stage cp.async pipeline. grid (8, 128, 2=dir).
// ---------------------------------------------------------------------------
#define OFF_A   0
#define OFF_ALO 16384
#define OFF_B   32768
#define STAGE   65536
#define SMEM_BYTES (3 * STAGE)   // 196608

__global__ void __launch_bounds__(512, 1)
gemm_hw_kernel(const float* __restrict__ fw_b, const float* __restrict__ bw_b,
               float* __restrict__ out, int l, int hw) {
    extern __shared__ char sm[];
    uint32_t sb = smem_to_u32(sm);
    int tid = threadIdx.x, wid = tid >> 5, lane = tid & 31;
    int wy = wid & 3, wx = wid >> 2;
    int jcta = blockIdx.x;
    int m0 = blockIdx.y * 128;
    int dir = blockIdx.z;
    int widx = dir * 4 + l * 2 + hw;
    const float* bias = (dir ? bw_b : fw_b) + (size_t)l * 2 * N2 + (size_t)hw * N2;
    const __half* xhi = g_xhi[dir];
    const __half* xlo = g_xlo[dir];
    const size_t wbase = (size_t)widx * 2048 * 1024 + (size_t)jcta * 256 * 1024;

    float acc[2][8][4];
#pragma unroll
    for (int mt = 0; mt < 2; mt++)
#pragma unroll
        for (int j = 0; j < 8; j++)
#pragma unroll
            for (int e = 0; e < 4; e++) acc[mt][j][e] = 0.f;

    // lane-invariant pieces of ldmatrix addresses
    int a_row  = wy * 32 + (lane & 15);           // + mt*16
    int a_colb = (lane >> 4) * 16;                // + ks*32
    int b_row  = wx * 64 + ((lane >> 4) << 3) + (lane & 7);  // + jp*16
    int b_colb = ((lane >> 3) & 1) * 16;          // + ks*32

#define LOAD_STAGE(c, stg) do { \
    int cc = (c); uint32_t so_base = (stg); \
    _Pragma("unroll") \
    for (int i = 0; i < 2; i++) { \
        int idx = tid + 512 * i; int row = idx >> 3, q = idx & 7; \
        size_t g = (size_t)(m0 + row) * Hz + cc * 64 + q * 8; \
        uint32_t so = SW128((uint32_t)(row * 128 + q * 16)); \
        cpasync16(sb + so_base + OFF_A + so, xhi + g); \
        cpasync16(sb + so_base + OFF_ALO + so, xlo + g); \
    } \
    _Pragma("unroll") \
    for (int i = 0; i < 4; i++) { \
        int idx = tid + 512 * i; int row = idx >> 3, q = idx & 7; \
        size_t g = wbase + (size_t)row * Hz + cc * 64 + q * 8; \
        uint32_t so = SW128((uint32_t)(row * 128 + q * 16)); \
        cpasync16(sb + so_base + OFF_B + so, g_Whi + g); \
    } \
    CP_COMMIT(); \
} while (0)

    LOAD_STAGE(0, 0);
    LOAD_STAGE(1, STAGE);

    for (int c = 0; c < 16; c++) {
        uint32_t stg = (c % 3) * STAGE;
        if (c + 2 < 16) {
            LOAD_STAGE(c + 2, ((c + 2) % 3) * STAGE);
            CP_WAIT(2);
        } else if (c + 1 < 16) {
            CP_WAIT(1);
        } else {
            CP_WAIT(0);
        }
        __syncthreads();

#pragma unroll
        for (int ks = 0; ks < 4; ks++) {
            uint32_t Ah[2][4], Al[2][4];
#pragma unroll
            for (int mt = 0; mt < 2; mt++) {
                uint32_t off = SW128((uint32_t)((a_row + mt * 16) * 128 +
                                                a_colb + ks * 32));
                ldsm4(Ah[mt], sb + stg + OFF_A + off);
                ldsm4(Al[mt], sb + stg + OFF_ALO + off);
            }
            uint32_t Bh[4][4];
#pragma unroll
            for (int jp = 0; jp < 4; jp++) {
                uint32_t off = SW128((uint32_t)((b_row + jp * 16) * 128 +
                                                b_colb + ks * 32));
                ldsm4(Bh[jp], sb + stg + OFF_B + off);
            }
#pragma unroll
            for (int mt = 0; mt < 2; mt++)
#pragma unroll
                for (int jp = 0; jp < 4; jp++) {
                    mma16816(acc[mt][2 * jp],     Ah[mt], Bh[jp] + 0);
                    mma16816(acc[mt][2 * jp + 1], Ah[mt], Bh[jp] + 2);
                    mma16816(acc[mt][2 * jp],     Al[mt], Bh[jp] + 0);
                    mma16816(acc[mt][2 * jp + 1], Al[mt], Bh[jp] + 2);
                }
        }
        __syncthreads();
    }

    // ---- fused highway epilogue (in registers) ----
    float* state = dir ? g_bo : g_fo;
    float* gx = g_x[dir];
#pragma unroll
    for (int mt = 0; mt < 2; mt++) {
        int r0 = m0 + wy * 32 + mt * 16 + (lane >> 2);
#pragma unroll
        for (int p = 0; p < 4; p++) {
            int h = jcta * 128 + wx * 32 + p * 8 + (lane & 3) * 2;
            float bn0 = bias[h],        bn1 = bias[h + 1];
            float bg0 = bias[1024 + h], bg1 = bias[1024 + h + 1];
            const float* nlr = acc[mt][2 * p];
            const float* gr  = acc[mt][2 * p + 1];
#pragma unroll
            for (int hf = 0; hf < 2; hf++) {
                int r = r0 + hf * 8;
                size_t gp = (size_t)r * Hz + h;
                float nl0 = nlr[hf * 2 + 0] + bn0;
                float nl1 = nlr[hf * 2 + 1] + bn1;
                float gg0 = gr[hf * 2 + 0] + bg0;
                float gg1 = gr[hf * 2 + 1] + bg1;
                float gs0 = 1.f / (1.f + __expf(-gg0));
                float gs1 = 1.f / (1.f + __expf(-gg1));
                float2 xo = *(const float2*)(gx + gp);
                float r0v = gs0 * xo.x + (1.f - gs0) * fmaxf(nl0, 0.f);
                float r1v = gs1 * xo.y + (1.f - gs1) * fmaxf(nl1, 0.f);
                if (hw == 0) {
                    *(float2*)(gx + gp) = make_float2(r0v, r1v);
                    __half b0 = __float2half(r0v);
                    __half b1 = __float2half(r1v);
                    ((__half2*)g_xhi[dir])[gp / 2] = __halves2half2(b0, b1);
                    ((__half2*)g_xlo[dir])[gp / 2] = __halves2half2(
                        __float2half(r0v - __half2float(b0)),
                        __float2half(r1v - __half2float(b1)));
                } else {
                    if (l) {
                        float2 st = *(const float2*)(state + gp);
                        r0v += st.x; r1v += st.y;
                    }
                    *(float2*)(state + gp) = make_float2(r0v, r1v);
                    *(float2*)(out + ((size_t)l * Mz + r) * N2 +
                               (size_t)dir * Hz + h) = make_float2(r0v, r1v);
                }
            }
        }
    }
}

// ---------------------------------------------------------------------------
extern "C" void kernel_launch(void* const* d_in, const int* in_sizes, int n_in,
                              void* d_out, int out_size) {
    const float* inputs = (const float*)d_in[0];
    const float* fw_pad = (const float*)d_in[2];
    const float* bw_pad = (const float*)d_in[3];
    const float* fw_w   = (const float*)d_in[4];
    const float* bw_w   = (const float*)d_in[5];
    const float* fw_W   = (const float*)d_in[6];
    const float* fw_b   = (const float*)d_in[7];
    const float* bw_W   = (const float*)d_in[8];
    const float* bw_b   = (const float*)d_in[9];
    float* out = (float*)d_out;

    cudaFuncSetAttribute(gemm_hw_kernel,
                         cudaFuncAttributeMaxDynamicSharedMemorySize, SMEM_BYTES);

    prep_w_kernel<<<dim3(64, 32, 8), dim3(32, 8)>>>(fw_W, bw_W);
    init_kernel<<<(size_t)Mz * Hz / 4 / 256, 256>>>(inputs);

    for (int l = 0; l < Lz; l++) {
        wsum_kernel<<<dim3(Mz, 2), 256>>>(fw_pad + (size_t)l * WD * Hz,
                                          bw_pad + (size_t)l * WD * Hz,
                                          fw_w + (size_t)l * (WD + 1),
                                          bw_w + (size_t)l * (WD + 1));
        for (int hw = 0; hw < 2; hw++) {
            gemm_hw_kernel<<<dim3(8, 128, 2), 512, SMEM_BYTES>>>(
                fw_b, bw_b, out, l, hw);
        }
    }
}

// round 10
// speedup vs baseline: 1.5333x; 1.1638x over previous
#include <cuda_runtime.h>
#include <cuda_fp16.h>
#include <math.h>
#include <stdint.h>

// Problem constants
#define Bz 32
#define Sz 512
#define Hz 1024
#define Lz 2
#define WD 4
#define Mz (Bz*Sz)        // 16384 rows
#define N2 (2*Hz)         // 2048 proj cols

#define SW128(off) ((off) ^ (((off) >> 3) & 0x70))

__device__ __forceinline__ uint32_t smem_to_u32(const void* p) {
    uint32_t a;
    asm("{ .reg .u64 t; cvta.to.shared.u64 t, %1; cvt.u32.u64 %0, t; }" : "=r"(a) : "l"(p));
    return a;
}

__device__ __forceinline__ void cpasync16(uint32_t dst, const void* src) {
    asm volatile("cp.async.cg.shared.global [%0], [%1], 16;" :: "r"(dst), "l"(src));
}
#define CP_COMMIT() asm volatile("cp.async.commit_group;" ::: "memory")
#define CP_WAIT(n)  asm volatile("cp.async.wait_group %0;" :: "n"(n) : "memory")

__device__ __forceinline__ void ldsm4(uint32_t* r, uint32_t addr) {
    asm volatile("ldmatrix.sync.aligned.m8n8.x4.shared.b16 {%0,%1,%2,%3}, [%4];"
        : "=r"(r[0]), "=r"(r[1]), "=r"(r[2]), "=r"(r[3]) : "r"(addr));
}

__device__ __forceinline__ void mma16816(float* c, const uint32_t* a, const uint32_t* b) {
    asm volatile("mma.sync.aligned.m16n8k16.row.col.f32.f16.f16.f32 "
        "{%0,%1,%2,%3}, {%4,%5,%6,%7}, {%8,%9}, {%0,%1,%2,%3};"
        : "+f"(c[0]), "+f"(c[1]), "+f"(c[2]), "+f"(c[3])
        : "r"(a[0]), "r"(a[1]), "r"(a[2]), "r"(a[3]), "r"(b[0]), "r"(b[1]));
}

// ---------------------------------------------------------------------------
// Scratch (device globals, allocation-free).
// Activation buffers are PING-PONGED per highway stage to eliminate the
// cross-CTA read/write race: [dir][buf] with buf 0 = wsum output (hw0 input),
// buf 1 = hw0 output (hw1 input). No kernel reads and writes the same buf.
// ---------------------------------------------------------------------------
__device__ float   g_fo[(size_t)Mz * Hz];
__device__ float   g_bo[(size_t)Mz * Hz];
__device__ float   g_x  [2][2][(size_t)Mz * Hz];
__device__ __half  g_xhi[2][2][(size_t)Mz * Hz];
__device__ __half  g_xlo[2][2][(size_t)Mz * Hz];
// Transposed fp16 weights: [widx=8][jblk=16][nn=128][k=1024]
// nn interleave within 64-hidden block: nl at (hp>>3)*16+(hp&7), gate +8.
__device__ __half  g_Whi[(size_t)8 * 2048 * 1024];

// ---------------------------------------------------------------------------
// prep_w: transpose + fp16 round + nl/gate 8-col interleave
// widx = dir*4 + l*2 + hw
// ---------------------------------------------------------------------------
__global__ void prep_w_kernel(const float* __restrict__ fw_W,
                              const float* __restrict__ bw_W) {
    int widx = blockIdx.z;
    const float* W = (widx >= 4 ? bw_W : fw_W) +
                     ((size_t)((widx >> 1) & 1) * 2 + (widx & 1)) * Hz * N2;
    __shared__ float tile[32][33];
    int k0 = blockIdx.y * 32, n0 = blockIdx.x * 32;
    int tx = threadIdx.x, ty = threadIdx.y;
#pragma unroll
    for (int i = 0; i < 4; i++) {
        int ky = ty + 8 * i;
        tile[ky][tx] = W[(size_t)(k0 + ky) * N2 + n0 + tx];
    }
    __syncthreads();
#pragma unroll
    for (int i = 0; i < 4; i++) {
        int ny = ty + 8 * i;
        int n = n0 + ny;
        int h = n & 1023;
        int half = n >> 10;           // 0 = nl, 1 = gate
        int jb = h >> 6;              // 16 column-blocks of 64 hidden
        int hp = h & 63;
        int p = (hp >> 3) * 16 + (hp & 7) + half * 8;   // 0..127
        size_t orow = ((size_t)widx * 2048 + jb * 128 + p) * Hz + k0 + tx;
        g_Whi[orow] = __float2half(tile[tx][ny]);
    }
}

// ---------------------------------------------------------------------------
// window sum -> g_x[dir][0] (float) + g_xhi/g_xlo[dir][0] (fp16 split)
// blockIdx.y = dir.  At l==0 the stream state IS the inputs array.
// ---------------------------------------------------------------------------
__global__ void wsum_kernel(const float* __restrict__ inputs,
                            const float* __restrict__ pf,
                            const float* __restrict__ pb,
                            const float* __restrict__ fw_w,
                            const float* __restrict__ bw_w, int l) {
    int dir = blockIdx.y;
    const float* o  = (l == 0) ? inputs : (dir ? g_bo : g_fo);
    const float* w5 = dir ? bw_w : fw_w;
    int m  = blockIdx.x;
    int t  = m & (Sz - 1);
    int h4 = threadIdx.x;
    float4 acc = make_float4(0.f, 0.f, 0.f, 0.f);
#pragma unroll
    for (int k = 0; k <= WD; k++) {
        int p = t + k + (dir ? 0 : -WD);
        const float4* src;
        if (p < 0)        src = (const float4*)(pf + (size_t)(p + WD) * Hz);
        else if (p >= Sz) src = (const float4*)(pb + (size_t)(p - Sz) * Hz);
        else              src = (const float4*)(o  + (size_t)(m - t + p) * Hz);
        float wk = w5[k];
        float4 v = src[h4];
        acc.x += wk * v.x; acc.y += wk * v.y;
        acc.z += wk * v.z; acc.w += wk * v.w;
    }
    size_t o4 = (size_t)m * (Hz / 4) + h4;
    ((float4*)g_x[dir][0])[o4] = acc;
    __half h0 = __float2half(acc.x), h1 = __float2half(acc.y);
    __half h2 = __float2half(acc.z), h3 = __float2half(acc.w);
    ((__half2*)g_xhi[dir][0])[o4 * 2 + 0] = __halves2half2(h0, h1);
    ((__half2*)g_xhi[dir][0])[o4 * 2 + 1] = __halves2half2(h2, h3);
    ((__half2*)g_xlo[dir][0])[o4 * 2 + 0] = __halves2half2(
        __float2half(acc.x - __half2float(h0)),
        __float2half(acc.y - __half2float(h1)));
    ((__half2*)g_xlo[dir][0])[o4 * 2 + 1] = __halves2half2(
        __float2half(acc.z - __half2float(h2)),
        __float2half(acc.w - __half2float(h3)));
}

// ---------------------------------------------------------------------------
// fp16 mma.sync GEMM (2-product: (Ahi+Alo)*Whi) + fused highway epilogue.
// CTA: 128 M x 128 proj (interleaved nl/gate), 256 thr, 8 warps (4M x 2N),
// warp tile 32x64, BK=64, 2-stage cp.async pipeline, 2 CTAs/SM.
// grid (16, 128, 2=dir). hw selects src buffer; hw0 writes buf 1 (ping-pong).
// ---------------------------------------------------------------------------
#define OFF_A   0
#define OFF_ALO 16384
#define OFF_B   32768
#define STAGE   49152
#define SMEM_BYTES (2 * STAGE)   // 98304 per CTA -> 2 CTAs/SM

__global__ void __launch_bounds__(256, 2)
gemm_hw_kernel(const float* __restrict__ fw_b, const float* __restrict__ bw_b,
               float* __restrict__ out, int l, int hw) {
    extern __shared__ char sm[];
    uint32_t sb = smem_to_u32(sm);
    int tid = threadIdx.x, wid = tid >> 5, lane = tid & 31;
    int wy = wid & 3, wx = wid >> 2;           // 4 M-warps x 2 N-warps
    int jcta = blockIdx.x;                     // 0..15 (64 hidden cols each)
    int m0 = blockIdx.y * 128;
    int dir = blockIdx.z;
    int widx = dir * 4 + l * 2 + hw;
    const float* bias = (dir ? bw_b : fw_b) + (size_t)l * 2 * N2 + (size_t)hw * N2;
    const __half* xhi = g_xhi[dir][hw];        // src buffer = hw
    const __half* xlo = g_xlo[dir][hw];
    const size_t wbase = (size_t)widx * 2048 * 1024 + (size_t)jcta * 128 * 1024;

    float acc[2][8][4];
#pragma unroll
    for (int mt = 0; mt < 2; mt++)
#pragma unroll
        for (int j = 0; j < 8; j++)
#pragma unroll
            for (int e = 0; e < 4; e++) acc[mt][j][e] = 0.f;

    // lane-invariant pieces of ldmatrix addresses
    int a_row  = wy * 32 + (lane & 15);                      // + mt*16
    int a_colb = (lane >> 4) * 16;                           // + ks*32
    int b_row  = wx * 64 + ((lane >> 4) << 3) + (lane & 7);  // + jp*16
    int b_colb = ((lane >> 3) & 1) * 16;                     // + ks*32

#define LOAD_STAGE(c, stg) do { \
    int cc = (c); uint32_t so_base = (stg); \
    _Pragma("unroll") \
    for (int i = 0; i < 4; i++) { \
        int idx = tid + 256 * i; int row = idx >> 3, q = idx & 7; \
        size_t gofs = (size_t)(m0 + row) * Hz + cc * 64 + q * 8; \
        uint32_t so = SW128((uint32_t)(row * 128 + q * 16)); \
        cpasync16(sb + so_base + OFF_A + so, xhi + gofs); \
        cpasync16(sb + so_base + OFF_ALO + so, xlo + gofs); \
        cpasync16(sb + so_base + OFF_B + so, \
                  g_Whi + wbase + (size_t)row * Hz + cc * 64 + q * 8); \
    } \
    CP_COMMIT(); \
} while (0)

    LOAD_STAGE(0, 0);

    for (int c = 0; c < 16; c++) {
        uint32_t stg = (c & 1) * STAGE;
        if (c + 1 < 16) {
            LOAD_STAGE(c + 1, ((c + 1) & 1) * STAGE);
            CP_WAIT(1);
        } else {
            CP_WAIT(0);
        }
        __syncthreads();

#pragma unroll
        for (int ks = 0; ks < 4; ks++) {
            uint32_t Ah[2][4], Al[2][4];
#pragma unroll
            for (int mt = 0; mt < 2; mt++) {
                uint32_t off = SW128((uint32_t)((a_row + mt * 16) * 128 +
                                                a_colb + ks * 32));
                ldsm4(Ah[mt], sb + stg + OFF_A + off);
                ldsm4(Al[mt], sb + stg + OFF_ALO + off);
            }
            uint32_t Bh[4][4];
#pragma unroll
            for (int jp = 0; jp < 4; jp++) {
                uint32_t off = SW128((uint32_t)((b_row + jp * 16) * 128 +
                                                b_colb + ks * 32));
                ldsm4(Bh[jp], sb + stg + OFF_B + off);
            }
#pragma unroll
            for (int mt = 0; mt < 2; mt++)
#pragma unroll
                for (int jp = 0; jp < 4; jp++) {
                    mma16816(acc[mt][2 * jp],     Ah[mt], Bh[jp] + 0);
                    mma16816(acc[mt][2 * jp + 1], Ah[mt], Bh[jp] + 2);
                    mma16816(acc[mt][2 * jp],     Al[mt], Bh[jp] + 0);
                    mma16816(acc[mt][2 * jp + 1], Al[mt], Bh[jp] + 2);
                }
        }
        __syncthreads();
    }

    // ---- fused highway epilogue (in registers) ----
    float* state = dir ? g_bo : g_fo;
    const float* gx_in = g_x[dir][hw];
#pragma unroll
    for (int mt = 0; mt < 2; mt++) {
        int r0 = m0 + wy * 32 + mt * 16 + (lane >> 2);
#pragma unroll
        for (int p = 0; p < 4; p++) {
            int h = jcta * 64 + wx * 32 + p * 8 + (lane & 3) * 2;
            float bn0 = bias[h],        bn1 = bias[h + 1];
            float bg0 = bias[1024 + h], bg1 = bias[1024 + h + 1];
            const float* nlr = acc[mt][2 * p];
            const float* gr  = acc[mt][2 * p + 1];
#pragma unroll
            for (int hf = 0; hf < 2; hf++) {
                int r = r0 + hf * 8;
                size_t gp = (size_t)r * Hz + h;
                float nl0 = nlr[hf * 2 + 0] + bn0;
                float nl1 = nlr[hf * 2 + 1] + bn1;
                float gg0 = gr[hf * 2 + 0] + bg0;
                float gg1 = gr[hf * 2 + 1] + bg1;
                float gs0 = 1.f / (1.f + __expf(-gg0));
                float gs1 = 1.f / (1.f + __expf(-gg1));
                float2 xo = *(const float2*)(gx_in + gp);
                float r0v = gs0 * xo.x + (1.f - gs0) * fmaxf(nl0, 0.f);
                float r1v = gs1 * xo.y + (1.f - gs1) * fmaxf(nl1, 0.f);
                if (hw == 0) {
                    // write NEW x to buffer 1 (ping-pong: no reader races)
                    *(float2*)(g_x[dir][1] + gp) = make_float2(r0v, r1v);
                    __half b0 = __float2half(r0v);
                    __half b1 = __float2half(r1v);
                    ((__half2*)g_xhi[dir][1])[gp / 2] = __halves2half2(b0, b1);
                    ((__half2*)g_xlo[dir][1])[gp / 2] = __halves2half2(
                        __float2half(r0v - __half2float(b0)),
                        __float2half(r1v - __half2float(b1)));
                } else {
                    if (l) {
                        float2 st = *(const float2*)(state + gp);
                        r0v += st.x; r1v += st.y;
                    }
                    *(float2*)(state + gp) = make_float2(r0v, r1v);
                    *(float2*)(out + ((size_t)l * Mz + r) * N2 +
                               (size_t)dir * Hz + h) = make_float2(r0v, r1v);
                }
            }
        }
    }
}

// ---------------------------------------------------------------------------
extern "C" void kernel_launch(void* const* d_in, const int* in_sizes, int n_in,
                              void* d_out, int out_size) {
    const float* inputs = (const float*)d_in[0];
    const float* fw_pad = (const float*)d_in[2];
    const float* bw_pad = (const float*)d_in[3];
    const float* fw_w   = (const float*)d_in[4];
    const float* bw_w   = (const float*)d_in[5];
    const float* fw_W   = (const float*)d_in[6];
    const float* fw_b   = (const float*)d_in[7];
    const float* bw_W   = (const float*)d_in[8];
    const float* bw_b   = (const float*)d_in[9];
    float* out = (float*)d_out;

    cudaFuncSetAttribute(gemm_hw_kernel,
                         cudaFuncAttributeMaxDynamicSharedMemorySize, SMEM_BYTES);

    prep_w_kernel<<<dim3(64, 32, 8), dim3(32, 8)>>>(fw_W, bw_W);

    for (int l = 0; l < Lz; l++) {
        wsum_kernel<<<dim3(Mz, 2), 256>>>(inputs,
                                          fw_pad + (size_t)l * WD * Hz,
                                          bw_pad + (size_t)l * WD * Hz,
                                          fw_w + (size_t)l * (WD + 1),
                                          bw_w + (size_t)l * (WD + 1), l);
        for (int hw = 0; hw < 2; hw++) {
            gemm_hw_kernel<<<dim3(16, 128, 2), 256, SMEM_BYTES>>>(
                fw_b, bw_b, out, l, hw);
        }
    }
}

// round 11
// speedup vs baseline: 2.5377x; 1.6551x over previous
#include <cuda_runtime.h>
#include <cuda_fp16.h>
#include <math.h>
#include <stdint.h>

// Problem constants
#define Bz 32
#define Sz 512
#define Hz 1024
#define Lz 2
#define WD 4
#define Mz (Bz*Sz)        // 16384 rows
#define N2 (2*Hz)         // 2048 proj cols

#define SW128(off) ((off) ^ (((off) >> 3) & 0x70))

__device__ __forceinline__ uint32_t smem_to_u32(const void* p) {
    uint32_t a;
    asm("{ .reg .u64 t; cvta.to.shared.u64 t, %1; cvt.u32.u64 %0, t; }" : "=r"(a) : "l"(p));
    return a;
}

__device__ __forceinline__ void cpasync16(uint32_t dst, const void* src) {
    asm volatile("cp.async.cg.shared.global [%0], [%1], 16;" :: "r"(dst), "l"(src));
}
#define CP_COMMIT() asm volatile("cp.async.commit_group;" ::: "memory")
#define CP_WAIT(n)  asm volatile("cp.async.wait_group %0;" :: "n"(n) : "memory")

__device__ __forceinline__ void ldsm4(uint32_t* r, uint32_t addr) {
    asm volatile("ldmatrix.sync.aligned.m8n8.x4.shared.b16 {%0,%1,%2,%3}, [%4];"
        : "=r"(r[0]), "=r"(r[1]), "=r"(r[2]), "=r"(r[3]) : "r"(addr));
}

__device__ __forceinline__ void mma16816(float* c, const uint32_t* a, const uint32_t* b) {
    asm volatile("mma.sync.aligned.m16n8k16.row.col.f32.f16.f16.f32 "
        "{%0,%1,%2,%3}, {%4,%5,%6,%7}, {%8,%9}, {%0,%1,%2,%3};"
        : "+f"(c[0]), "+f"(c[1]), "+f"(c[2]), "+f"(c[3])
        : "r"(a[0]), "r"(a[1]), "r"(a[2]), "r"(a[3]), "r"(b[0]), "r"(b[1]));
}

// ---------------------------------------------------------------------------
// Scratch (device globals, allocation-free).
// Activation buffers PING-PONGED per highway stage (race-free by construction):
// buf 0 = wsum output (hw0 input), buf 1 = hw0 output (hw1 input).
// ---------------------------------------------------------------------------
__device__ float   g_fo[(size_t)Mz * Hz];
__device__ float   g_bo[(size_t)Mz * Hz];
__device__ float   g_x  [2][2][(size_t)Mz * Hz];
__device__ __half  g_xhi[2][2][(size_t)Mz * Hz];
// Transposed fp16 weights: [widx=8][jblk=16][nn=128][k=1024]
// nn interleave within 64-hidden block: nl at (hp>>3)*16+(hp&7), gate +8.
__device__ __half  g_Whi[(size_t)8 * 2048 * 1024];

// ---------------------------------------------------------------------------
// prep_w: transpose + fp16 round + nl/gate 8-col interleave
// widx = dir*4 + l*2 + hw
// ---------------------------------------------------------------------------
__global__ void prep_w_kernel(const float* __restrict__ fw_W,
                              const float* __restrict__ bw_W) {
    int widx = blockIdx.z;
    const float* W = (widx >= 4 ? bw_W : fw_W) +
                     ((size_t)((widx >> 1) & 1) * 2 + (widx & 1)) * Hz * N2;
    __shared__ float tile[32][33];
    int k0 = blockIdx.y * 32, n0 = blockIdx.x * 32;
    int tx = threadIdx.x, ty = threadIdx.y;
#pragma unroll
    for (int i = 0; i < 4; i++) {
        int ky = ty + 8 * i;
        tile[ky][tx] = W[(size_t)(k0 + ky) * N2 + n0 + tx];
    }
    __syncthreads();
#pragma unroll
    for (int i = 0; i < 4; i++) {
        int ny = ty + 8 * i;
        int n = n0 + ny;
        int h = n & 1023;
        int half = n >> 10;           // 0 = nl, 1 = gate
        int jb = h >> 6;              // 16 column-blocks of 64 hidden
        int hp = h & 63;
        int p = (hp >> 3) * 16 + (hp & 7) + half * 8;   // 0..127
        size_t orow = ((size_t)widx * 2048 + jb * 128 + p) * Hz + k0 + tx;
        g_Whi[orow] = __float2half(tile[tx][ny]);
    }
}

// ---------------------------------------------------------------------------
// window sum -> g_x[dir][0] (float) + g_xhi[dir][0] (fp16)
// blockIdx.y = dir.  At l==0 the stream state IS the inputs array.
// ---------------------------------------------------------------------------
__global__ void wsum_kernel(const float* __restrict__ inputs,
                            const float* __restrict__ pf,
                            const float* __restrict__ pb,
                            const float* __restrict__ fw_w,
                            const float* __restrict__ bw_w, int l) {
    int dir = blockIdx.y;
    const float* o  = (l == 0) ? inputs : (dir ? g_bo : g_fo);
    const float* w5 = dir ? bw_w : fw_w;
    int m  = blockIdx.x;
    int t  = m & (Sz - 1);
    int h4 = threadIdx.x;
    float4 acc = make_float4(0.f, 0.f, 0.f, 0.f);
#pragma unroll
    for (int k = 0; k <= WD; k++) {
        int p = t + k + (dir ? 0 : -WD);
        const float4* src;
        if (p < 0)        src = (const float4*)(pf + (size_t)(p + WD) * Hz);
        else if (p >= Sz) src = (const float4*)(pb + (size_t)(p - Sz) * Hz);
        else              src = (const float4*)(o  + (size_t)(m - t + p) * Hz);
        float wk = w5[k];
        float4 v = src[h4];
        acc.x += wk * v.x; acc.y += wk * v.y;
        acc.z += wk * v.z; acc.w += wk * v.w;
    }
    size_t o4 = (size_t)m * (Hz / 4) + h4;
    ((float4*)g_x[dir][0])[o4] = acc;
    ((__half2*)g_xhi[dir][0])[o4 * 2 + 0] =
        __halves2half2(__float2half(acc.x), __float2half(acc.y));
    ((__half2*)g_xhi[dir][0])[o4 * 2 + 1] =
        __halves2half2(__float2half(acc.z), __float2half(acc.w));
}

// ---------------------------------------------------------------------------
// fp16 mma.sync GEMM (single product) + fused highway epilogue.
// CTA: 128 M x 128 proj (interleaved nl/gate), 256 thr, 8 warps (4M x 2N),
// warp tile 32x64, BK=64, 3-stage cp.async pipeline, 2 CTAs/SM.
// grid (16, 128, 2=dir). hw selects src buffer; hw0 writes buf 1 (ping-pong).
// ---------------------------------------------------------------------------
#define OFF_A   0
#define OFF_B   16384
#define STAGE   32768
#define SMEM_BYTES (3 * STAGE)   // 98304 per CTA -> 2 CTAs/SM

__global__ void __launch_bounds__(256, 2)
gemm_hw_kernel(const float* __restrict__ fw_b, const float* __restrict__ bw_b,
               float* __restrict__ out, int l, int hw) {
    extern __shared__ char sm[];
    uint32_t sb = smem_to_u32(sm);
    int tid = threadIdx.x, wid = tid >> 5, lane = tid & 31;
    int wy = wid & 3, wx = wid >> 2;           // 4 M-warps x 2 N-warps
    int jcta = blockIdx.x;                     // 0..15 (64 hidden cols each)
    int m0 = blockIdx.y * 128;
    int dir = blockIdx.z;
    int widx = dir * 4 + l * 2 + hw;
    const float* bias = (dir ? bw_b : fw_b) + (size_t)l * 2 * N2 + (size_t)hw * N2;
    const __half* xhi = g_xhi[dir][hw];        // src buffer = hw
    const size_t wbase = (size_t)widx * 2048 * 1024 + (size_t)jcta * 128 * 1024;

    float acc[2][8][4];
#pragma unroll
    for (int mt = 0; mt < 2; mt++)
#pragma unroll
        for (int j = 0; j < 8; j++)
#pragma unroll
            for (int e = 0; e < 4; e++) acc[mt][j][e] = 0.f;

    // lane-invariant pieces of ldmatrix addresses
    int a_row  = wy * 32 + (lane & 15);                      // + mt*16
    int a_colb = (lane >> 4) * 16;                           // + ks*32
    int b_row  = wx * 64 + ((lane >> 4) << 3) + (lane & 7);  // + jp*16
    int b_colb = ((lane >> 3) & 1) * 16;                     // + ks*32

#define LOAD_STAGE(c, stg) do { \
    int cc = (c); uint32_t so_base = (stg); \
    _Pragma("unroll") \
    for (int i = 0; i < 4; i++) { \
        int idx = tid + 256 * i; int row = idx >> 3, q = idx & 7; \
        uint32_t so = SW128((uint32_t)(row * 128 + q * 16)); \
        cpasync16(sb + so_base + OFF_A + so, \
                  xhi + (size_t)(m0 + row) * Hz + cc * 64 + q * 8); \
        cpasync16(sb + so_base + OFF_B + so, \
                  g_Whi + wbase + (size_t)row * Hz + cc * 64 + q * 8); \
    } \
    CP_COMMIT(); \
} while (0)

    LOAD_STAGE(0, 0);
    LOAD_STAGE(1, STAGE);

    for (int c = 0; c < 16; c++) {
        uint32_t stg = (c % 3) * STAGE;
        if (c + 2 < 16) {
            LOAD_STAGE(c + 2, ((c + 2) % 3) * STAGE);
            CP_WAIT(2);
        } else if (c + 1 < 16) {
            CP_WAIT(1);
        } else {
            CP_WAIT(0);
        }
        __syncthreads();

#pragma unroll
        for (int ks = 0; ks < 4; ks++) {
            uint32_t Ah[2][4];
#pragma unroll
            for (int mt = 0; mt < 2; mt++) {
                uint32_t off = SW128((uint32_t)((a_row + mt * 16) * 128 +
                                                a_colb + ks * 32));
                ldsm4(Ah[mt], sb + stg + OFF_A + off);
            }
            uint32_t Bh[4][4];
#pragma unroll
            for (int jp = 0; jp < 4; jp++) {
                uint32_t off = SW128((uint32_t)((b_row + jp * 16) * 128 +
                                                b_colb + ks * 32));
                ldsm4(Bh[jp], sb + stg + OFF_B + off);
            }
#pragma unroll
            for (int mt = 0; mt < 2; mt++)
#pragma unroll
                for (int jp = 0; jp < 4; jp++) {
                    mma16816(acc[mt][2 * jp],     Ah[mt], Bh[jp] + 0);
                    mma16816(acc[mt][2 * jp + 1], Ah[mt], Bh[jp] + 2);
                }
        }
        __syncthreads();
    }

    // ---- fused highway epilogue (in registers) ----
    float* state = dir ? g_bo : g_fo;
    const float* gx_in = g_x[dir][hw];
#pragma unroll
    for (int mt = 0; mt < 2; mt++) {
        int r0 = m0 + wy * 32 + mt * 16 + (lane >> 2);
#pragma unroll
        for (int p = 0; p < 4; p++) {
            int h = jcta * 64 + wx * 32 + p * 8 + (lane & 3) * 2;
            float bn0 = bias[h],        bn1 = bias[h + 1];
            float bg0 = bias[1024 + h], bg1 = bias[1024 + h + 1];
            const float* nlr = acc[mt][2 * p];
            const float* gr  = acc[mt][2 * p + 1];
#pragma unroll
            for (int hf = 0; hf < 2; hf++) {
                int r = r0 + hf * 8;
                size_t gp = (size_t)r * Hz + h;
                float nl0 = nlr[hf * 2 + 0] + bn0;
                float nl1 = nlr[hf * 2 + 1] + bn1;
                float gg0 = gr[hf * 2 + 0] + bg0;
                float gg1 = gr[hf * 2 + 1] + bg1;
                float gs0 = 1.f / (1.f + __expf(-gg0));
                float gs1 = 1.f / (1.f + __expf(-gg1));
                float2 xo = *(const float2*)(gx_in + gp);
                float r0v = gs0 * xo.x + (1.f - gs0) * fmaxf(nl0, 0.f);
                float r1v = gs1 * xo.y + (1.f - gs1) * fmaxf(nl1, 0.f);
                if (hw == 0) {
                    // write NEW x to buffer 1 (ping-pong: no reader races)
                    *(float2*)(g_x[dir][1] + gp) = make_float2(r0v, r1v);
                    ((__half2*)g_xhi[dir][1])[gp / 2] = __halves2half2(
                        __float2half(r0v), __float2half(r1v));
                } else {
                    if (l) {
                        float2 st = *(const float2*)(state + gp);
                        r0v += st.x; r1v += st.y;
                    }
                    *(float2*)(state + gp) = make_float2(r0v, r1v);
                    *(float2*)(out + ((size_t)l * Mz + r) * N2 +
                               (size_t)dir * Hz + h) = make_float2(r0v, r1v);
                }
            }
        }
    }
}

// ---------------------------------------------------------------------------
extern "C" void kernel_launch(void* const* d_in, const int* in_sizes, int n_in,
                              void* d_out, int out_size) {
    const float* inputs = (const float*)d_in[0];
    const float* fw_pad = (const float*)d_in[2];
    const float* bw_pad = (const float*)d_in[3];
    const float* fw_w   = (const float*)d_in[4];
    const float* bw_w   = (const float*)d_in[5];
    const float* fw_W   = (const float*)d_in[6];
    const float* fw_b   = (const float*)d_in[7];
    const float* bw_W   = (const float*)d_in[8];
    const float* bw_b   = (const float*)d_in[9];
    float* out = (float*)d_out;

    cudaFuncSetAttribute(gemm_hw_kernel,
                         cudaFuncAttributeMaxDynamicSharedMemorySize, SMEM_BYTES);

    prep_w_kernel<<<dim3(64, 32, 8), dim3(32, 8)>>>(fw_W, bw_W);

    for (int l = 0; l < Lz; l++) {
        wsum_kernel<<<dim3(Mz, 2), 256>>>(inputs,
                                          fw_pad + (size_t)l * WD * Hz,
                                          bw_pad + (size_t)l * WD * Hz,
                                          fw_w + (size_t)l * (WD + 1),
                                          bw_w + (size_t)l * (WD + 1), l);
        for (int hw = 0; hw < 2; hw++) {
            gemm_hw_kernel<<<dim3(16, 128, 2), 256, SMEM_BYTES>>>(
                fw_b, bw_b, out, l, hw);
        }
    }
}